// round 2
// baseline (speedup 1.0000x reference)
#include <cuda_runtime.h>
#include <math.h>

#define DD 512
#define NN 128

// Snapshots of the N x N conditional state Omega before each 32-site block,
// plus per-row picked probabilities for the log-prob reduction.
__device__ float g_snap[16][NN * NN];
__device__ float g_picked[NN];

// ---------------------------------------------------------------------------
// Chain kernel: single CTA sweeps sites 0..D-1, conditioning each site to its
// true state (particle if in positions, else hole) via rank-1 updates of the
// 128x128 matrix Omega (K_cond = P Omega P^T). Stores Omega snapshot before
// every 32-site block. Omega rows are held in registers: thread (r,h) owns
// Omega[r][h*64 .. h*64+63].
// ---------------------------------------------------------------------------
__global__ void __launch_bounds__(256, 1)
chain_kernel(const float* __restrict__ P, const int* __restrict__ pos)
{
    __shared__ float pv[NN];
    __shared__ float wfin[NN];
    __shared__ float wpart[256];
    __shared__ float beta_parts[4];
    __shared__ unsigned char occ[DD];

    const int tid = threadIdx.x;
    const int r = tid & 127;
    const int h = tid >> 7;

    for (int i = tid; i < DD; i += 256) occ[i] = 0;
    __syncthreads();
    if (tid < NN) occ[pos[tid]] = 1;
    // occ first read deep inside the loop, after later barriers.

    float A[64];
#pragma unroll
    for (int c = 0; c < 64; c++) A[c] = (r == h * 64 + c) ? 1.0f : 0.0f;

    for (int i = 0; i < DD; i++) {
        if ((i & 31) == 0) {
            float* dst = &g_snap[i >> 5][r * NN + h * 64];
#pragma unroll
            for (int c = 0; c < 64; c++) dst[c] = A[c];
        }
        if (tid < NN) pv[tid] = P[i * NN + tid];
        __syncthreads();

        float acc = 0.0f;
#pragma unroll
        for (int c = 0; c < 64; c++) acc += A[c] * pv[h * 64 + c];
        wpart[tid] = acc;
        __syncthreads();

        if (h == 0) {
            float w = wpart[r] + wpart[r + 128];
            wfin[r] = w;
            float t = w * pv[r];
#pragma unroll
            for (int o = 16; o; o >>= 1) t += __shfl_xor_sync(0xffffffffu, t, o);
            if ((r & 31) == 0) beta_parts[r >> 5] = t;
        }
        __syncthreads();

        float beta = beta_parts[0] + beta_parts[1] + beta_parts[2] + beta_parts[3];
        float denom = occ[i] ? beta : (beta - 1.0f);
        float coef = 1.0f / denom;
        float s = coef * wfin[r];
#pragma unroll
        for (int c = 0; c < 64; c++) A[c] -= s * wfin[h * 64 + c];
        // No trailing barrier needed: next iteration's writes to pv/wpart/wfin
        // all happen after barriers every thread must pass.
    }
}

// ---------------------------------------------------------------------------
// Excursion kernel: one CTA per row k. Restart from the snapshot at the block
// containing xmin_k, replay the <=31 prefix sites with their true pattern,
// then hole-condition through the window [xmin_k, xmax_k), emitting
// probs[k,i] = c * beta and updating c *= (1 - beta). The last window site is
// forced (beta -> 1): emit, then stop without the singular update.
// ---------------------------------------------------------------------------
__global__ void __launch_bounds__(256, 1)
excursion_kernel(const float* __restrict__ P, const int* __restrict__ pos,
                 float* __restrict__ out)
{
    __shared__ float pv[NN];
    __shared__ float wfin[NN];
    __shared__ float wpart[256];
    __shared__ float beta_parts[4];
    __shared__ unsigned char occ[DD];
    __shared__ float row[DD];

    const int k = blockIdx.x;
    const int tid = threadIdx.x;
    const int r = tid & 127;
    const int h = tid >> 7;

    const int myPos = pos[k];
    const int xmin = (k == 0) ? 0 : (pos[k - 1] + 1);
    const int xmax = DD - NN + k + 1;
    const int b = xmin >> 5;
    const int s0 = b << 5;

    for (int i = tid; i < DD; i += 256) { occ[i] = 0; row[i] = 0.0f; }
    __syncthreads();
    if (tid < NN) occ[pos[tid]] = 1;

    float A[64];
    {
        const float* src = &g_snap[b][r * NN + h * 64];
#pragma unroll
        for (int c = 0; c < 64; c++) A[c] = src[c];
    }
    __syncthreads();  // occ ready before first use

    float cprod = 1.0f;
    for (int i = s0; i < xmax; i++) {
        if (tid < NN) pv[tid] = P[i * NN + tid];
        __syncthreads();

        float acc = 0.0f;
#pragma unroll
        for (int c = 0; c < 64; c++) acc += A[c] * pv[h * 64 + c];
        wpart[tid] = acc;
        __syncthreads();

        if (h == 0) {
            float w = wpart[r] + wpart[r + 128];
            wfin[r] = w;
            float t = w * pv[r];
#pragma unroll
            for (int o = 16; o; o >>= 1) t += __shfl_xor_sync(0xffffffffu, t, o);
            if ((r & 31) == 0) beta_parts[r >> 5] = t;
        }
        __syncthreads();

        float beta = beta_parts[0] + beta_parts[1] + beta_parts[2] + beta_parts[3];
        bool inwin = (i >= xmin);
        if (inwin) {
            float prob = cprod * beta;
            float pcl = (fabsf(prob) > 1e-15f) ? prob : 0.0f;
            if (tid == 0) {
                row[i] = pcl;
                if (i == myPos) g_picked[k] = pcl;
            }
            cprod *= (1.0f - beta);
            if (i == xmax - 1) break;  // forced site: skip singular update
        }
        // In-window sites are conditioned as holes (row k's matrix A_k has no
        // particle at positions[k]); prefix sites use the true pattern.
        float denom = (!inwin && occ[i]) ? beta : (beta - 1.0f);
        float coef = 1.0f / denom;
        float s = coef * wfin[r];
#pragma unroll
        for (int c = 0; c < 64; c++) A[c] -= s * wfin[h * 64 + c];
    }
    __syncthreads();
    for (int i = tid; i < DD; i += 256) out[k * DD + i] = row[i];
}

// ---------------------------------------------------------------------------
// Deterministic sequential log-sum of picked probabilities.
// ---------------------------------------------------------------------------
__global__ void logsum_kernel(float* __restrict__ out_scalar)
{
    if (threadIdx.x == 0 && blockIdx.x == 0) {
        float s = 0.0f;
        for (int k = 0; k < NN; k++) s += logf(g_picked[k]);
        *out_scalar = s;
    }
}

extern "C" void kernel_launch(void* const* d_in, const int* in_sizes, int n_in,
                              void* d_out, int out_size)
{
    const float* P = (const float*)d_in[0];    // [D, N] float32
    const int* pos = (const int*)d_in[1];      // [N] int32, sorted
    float* out = (float*)d_out;                // [N*D probs][1 logprob]

    chain_kernel<<<1, 256>>>(P, pos);
    excursion_kernel<<<NN, 256>>>(P, pos, out);
    logsum_kernel<<<1, 32>>>(out + (out_size - 1));
}

// round 3
// speedup vs baseline: 1.4871x; 1.4871x over previous
#include <cuda_runtime.h>
#include <math.h>

#define DD 512
#define NN 128

__device__ float g_picked[NN];

// ---- packed f32x2 helpers (Blackwell FFMA2 path, PTX-only) -----------------
static __device__ __forceinline__ unsigned long long ffma2(
    unsigned long long a, unsigned long long b, unsigned long long c)
{
    unsigned long long d;
    asm("fma.rn.f32x2 %0, %1, %2, %3;" : "=l"(d) : "l"(a), "l"(b), "l"(c));
    return d;
}
static __device__ __forceinline__ unsigned long long pack2(float x, float y)
{
    unsigned long long d;
    asm("mov.b64 %0, {%1, %2};" : "=l"(d) : "f"(x), "f"(y));
    return d;
}
static __device__ __forceinline__ void unpack2(unsigned long long v, float& x, float& y)
{
    asm("mov.b64 {%0, %1}, %2;" : "=f"(x), "=f"(y) : "l"(v));
}

// ---------------------------------------------------------------------------
// One CTA per output row k. Each CTA independently conditions the projection
// kernel K = P Omega P^T (Omega 128x128, register-resident) from scratch:
//   sites i < xmin_k : condition on the true pattern (rank-1 Sherman-Morrison)
//   sites in window  : emit probs[k,i] = c * beta, c *= (1-beta), hole-update
// Total steps per CTA = xmax_k <= 512, fully parallel across 128 SMs.
// Thread (r,h) owns Omega[r][h*64 .. h*64+63] as 32 packed f32x2 registers.
// ---------------------------------------------------------------------------
__global__ void __launch_bounds__(256, 1)
sampler_kernel(const float* __restrict__ P, const int* __restrict__ pos,
               float* __restrict__ out)
{
    __shared__ __align__(16) float pv[2][NN];
    __shared__ __align__(16) float wpart[256];
    __shared__ __align__(16) float wfin[NN];
    __shared__ float bparts[8];
    __shared__ unsigned char occ[DD];

    const int k    = blockIdx.x;
    const int tid  = threadIdx.x;
    const int r    = tid & 127;
    const int h    = tid >> 7;
    const int lane = tid & 31;
    const int wid  = tid >> 5;

    for (int i = tid; i < DD; i += 256) occ[i] = 0;
    __syncthreads();
    if (tid < NN) occ[pos[tid]] = 1;

    const int myPos = pos[k];
    const int xmin  = (k == 0) ? 0 : (pos[k - 1] + 1);
    const int xmax  = DD - NN + k + 1;

    // zero this CTA's output row (out is poisoned)
    for (int i = tid; i < DD; i += 256) out[k * DD + i] = 0.0f;

    // Omega = I
    unsigned long long A2[32];
#pragma unroll
    for (int j = 0; j < 32; j++) {
        int c0 = h * 64 + 2 * j;
        A2[j] = pack2((c0 == r) ? 1.0f : 0.0f, (c0 + 1 == r) ? 1.0f : 0.0f);
    }

    // prologue: stage P row 0, prefetch row 1
    float pnext = 0.0f;
    if (tid < NN) {
        pv[0][tid] = __ldg(&P[tid]);
        pnext      = __ldg(&P[NN + tid]);
    }
    __syncthreads();

    float cprod = 1.0f;
    int cur = 0;
    for (int i = 0; i < xmax; i++) {
        const float* pvc = pv[cur];
        const unsigned long long* pv2 =
            (const unsigned long long*)(pvc + h * 64);

        // w-partial: acc = sum_c Omega[r][h64+c] * p[h64+c]   (32 FFMA2)
        unsigned long long a0 = 0ull, a1 = 0ull, a2 = 0ull, a3 = 0ull;
#pragma unroll
        for (int j = 0; j < 32; j += 4) {
            a0 = ffma2(A2[j],     pv2[j],     a0);
            a1 = ffma2(A2[j + 1], pv2[j + 1], a1);
            a2 = ffma2(A2[j + 2], pv2[j + 2], a2);
            a3 = ffma2(A2[j + 3], pv2[j + 3], a3);
        }
        float x0, y0, x1, y1, x2, y2, x3, y3;
        unpack2(a0, x0, y0); unpack2(a1, x1, y1);
        unpack2(a2, x2, y2); unpack2(a3, x3, y3);
        float acc = ((x0 + y0) + (x1 + y1)) + ((x2 + y2) + (x3 + y3));

        // beta partial from registers; shfl tree starts pre-barrier
        float t = acc * pvc[r];
#pragma unroll
        for (int o = 16; o; o >>= 1) t += __shfl_xor_sync(0xffffffffu, t, o);
        if (lane == 0) bparts[wid] = t;

        wpart[tid] = acc;
        if (tid < NN) pv[cur ^ 1][tid] = pnext;   // stage next row
        __syncthreads();                           // --- b1 ---

        if (tid < NN && i + 2 < DD) pnext = __ldg(&P[(i + 2) * NN + tid]);

        float beta = ((bparts[0] + bparts[1]) + (bparts[2] + bparts[3]))
                   + ((bparts[4] + bparts[5]) + (bparts[6] + bparts[7]));

        if (h == 0) wfin[r] = wpart[r] + wpart[r + 128];
        float wr = wpart[r] + wpart[r + 128];

        bool inwin = (i >= xmin);
        if (inwin) {
            float prob = cprod * beta;
            if (tid == 0) {
                float pcl = (fabsf(prob) > 1e-15f) ? prob : 0.0f;
                out[k * DD + i] = pcl;
                if (i == myPos) g_picked[k] = pcl;
            }
            cprod *= (1.0f - beta);
            if (i == xmax - 1) break;   // forced last site: skip singular update
        }

        // prefix sites use the true pattern; window sites condition as holes
        float denom = (!inwin && occ[i]) ? beta : (beta - 1.0f);
        float s = (1.0f / denom) * wr;
        unsigned long long ns2 = pack2(-s, -s);

        __syncthreads();                           // --- b2 ---

        const unsigned long long* w2 = (const unsigned long long*)(wfin + h * 64);
#pragma unroll
        for (int j = 0; j < 32; j++) A2[j] = ffma2(ns2, w2[j], A2[j]);

        cur ^= 1;
    }
}

// ---------------------------------------------------------------------------
// Deterministic sequential log-sum of picked probabilities.
// ---------------------------------------------------------------------------
__global__ void logsum_kernel(float* __restrict__ out_scalar)
{
    if (threadIdx.x == 0 && blockIdx.x == 0) {
        float s = 0.0f;
        for (int k = 0; k < NN; k++) s += logf(g_picked[k]);
        *out_scalar = s;
    }
}

extern "C" void kernel_launch(void* const* d_in, const int* in_sizes, int n_in,
                              void* d_out, int out_size)
{
    const float* P = (const float*)d_in[0];    // [D, N] float32
    const int* pos = (const int*)d_in[1];      // [N] int32, sorted
    float* out = (float*)d_out;                // [N*D probs][1 logprob]

    sampler_kernel<<<NN, 256>>>(P, pos, out);
    logsum_kernel<<<1, 32>>>(out + (out_size - 1));
}

// round 4
// speedup vs baseline: 2.5366x; 1.7057x over previous
#include <cuda_runtime.h>
#include <math.h>

#define DD 512
#define NN 128

typedef unsigned long long ull;

__device__ float g_picked[NN];

// ---- packed f32x2 helpers (Blackwell FFMA2 path, PTX-only) -----------------
static __device__ __forceinline__ ull ffma2(ull a, ull b, ull c)
{
    ull d;
    asm("fma.rn.f32x2 %0, %1, %2, %3;" : "=l"(d) : "l"(a), "l"(b), "l"(c));
    return d;
}
static __device__ __forceinline__ ull pack2(float x, float y)
{
    ull d;
    asm("mov.b64 %0, {%1, %2};" : "=l"(d) : "f"(x), "f"(y));
    return d;
}
static __device__ __forceinline__ void unpack2(ull v, float& x, float& y)
{
    asm("mov.b64 {%0, %1}, %2;" : "=f"(x), "=f"(y) : "l"(v));
}

// ---------------------------------------------------------------------------
// One CTA (512 threads) per output row k. Each CTA independently conditions
// the projection kernel K = P Omega P^T (Omega 128x128, register-resident):
//   sites i < xmin_k : condition on the true pattern (rank-1 Sherman-Morrison)
//   window sites     : emit probs[k,i] = c * beta, c *= (1-beta), hole-update
// Thread (r,h) owns Omega[r][h*32 .. h*32+31] as 16 packed f32x2 registers.
// All shared-memory broadcasts are LDS.128 (ulonglong2).
// ---------------------------------------------------------------------------
__global__ void __launch_bounds__(512, 1)
sampler_kernel(const float* __restrict__ P, const int* __restrict__ pos,
               float* __restrict__ out)
{
    __shared__ __align__(16) float pv[2][NN];
    __shared__ __align__(16) float wpart[512];
    __shared__ __align__(16) float wfin[NN];
    __shared__ float bparts[16];
    __shared__ unsigned char occ[DD];

    const int k    = blockIdx.x;
    const int tid  = threadIdx.x;
    const int r    = tid & 127;
    const int h    = tid >> 7;        // 0..3 column quarter
    const int lane = tid & 31;
    const int wid  = tid >> 5;        // 0..15

    for (int i = tid; i < DD; i += 512) occ[i] = 0;
    __syncthreads();
    if (tid < NN) occ[pos[tid]] = 1;

    const int myPos = pos[k];
    const int xmin  = (k == 0) ? 0 : (pos[k - 1] + 1);
    const int xmax  = DD - NN + k + 1;

    // zero this CTA's output row (out is poisoned)
    for (int i = tid; i < DD; i += 512) out[k * DD + i] = 0.0f;

    // Omega = I ; thread owns cols c0 = h*32 + 2j, c0+1
    ull A2[16];
#pragma unroll
    for (int j = 0; j < 16; j++) {
        int c0 = h * 32 + 2 * j;
        A2[j] = pack2((c0 == r) ? 1.0f : 0.0f, (c0 + 1 == r) ? 1.0f : 0.0f);
    }

    // prologue: stage P row 0, prefetch row 1 (occ also covered by this barrier)
    float pnext = 0.0f;
    if (tid < NN) {
        pv[0][tid] = __ldg(&P[tid]);
        pnext      = __ldg(&P[NN + tid]);
    }
    __syncthreads();

    float cprod = 1.0f;
    int cur = 0;
    for (int i = 0; i < xmax; i++) {
        const float* pvc = pv[cur];
        const ulonglong2* pv4 = (const ulonglong2*)(pvc + h * 32);

        // acc = sum over 32 owned cols of Omega[r][c] * p[c]  (8x LDS.128, 16 FFMA2)
        ull a0 = 0ull, a1 = 0ull, a2 = 0ull, a3 = 0ull;
#pragma unroll
        for (int j = 0; j < 8; j += 2) {
            ulonglong2 u = pv4[j];
            ulonglong2 v = pv4[j + 1];
            a0 = ffma2(A2[2 * j],     u.x, a0);
            a1 = ffma2(A2[2 * j + 1], u.y, a1);
            a2 = ffma2(A2[2 * j + 2], v.x, a2);
            a3 = ffma2(A2[2 * j + 3], v.y, a3);
        }
        float x0, y0, x1, y1, x2, y2, x3, y3;
        unpack2(a0, x0, y0); unpack2(a1, x1, y1);
        unpack2(a2, x2, y2); unpack2(a3, x3, y3);
        float acc = ((x0 + y0) + (x1 + y1)) + ((x2 + y2) + (x3 + y3));

        // beta partial: sum over all 512 threads of acc * p[r] = p^T Omega p
        float t = acc * pvc[r];
#pragma unroll
        for (int o = 16; o; o >>= 1) t += __shfl_xor_sync(0xffffffffu, t, o);
        if (lane == 0) bparts[wid] = t;

        wpart[tid] = acc;
        if (tid < NN) pv[cur ^ 1][tid] = pnext;   // stage next row
        __syncthreads();                           // --- b1 ---

        if (tid < NN && i + 2 < DD) pnext = __ldg(&P[(i + 2) * NN + tid]);

        float beta = (((bparts[0] + bparts[1]) + (bparts[2] + bparts[3]))
                    + ((bparts[4] + bparts[5]) + (bparts[6] + bparts[7])))
                   + (((bparts[8] + bparts[9]) + (bparts[10] + bparts[11]))
                    + ((bparts[12] + bparts[13]) + (bparts[14] + bparts[15])));

        if (tid < NN)
            wfin[tid] = (wpart[tid] + wpart[tid + 128])
                      + (wpart[tid + 256] + wpart[tid + 384]);

        bool inwin = (i >= xmin);
        if (inwin) {
            if (tid == 0) {
                float prob = cprod * beta;
                float pcl = (fabsf(prob) > 1e-15f) ? prob : 0.0f;
                out[k * DD + i] = pcl;
                if (i == myPos) g_picked[k] = pcl;
            }
            cprod *= (1.0f - beta);
            if (i == xmax - 1) break;   // forced last site: skip singular update
        }

        // prefix sites use the true pattern; window sites condition as holes
        float denom = (!inwin && occ[i]) ? beta : (beta - 1.0f);
        float rden = 1.0f / denom;

        __syncthreads();                           // --- b2 ---

        float s = wfin[r] * rden;
        ull ns2 = pack2(-s, -s);
        const ulonglong2* w4 = (const ulonglong2*)(wfin + h * 32);
#pragma unroll
        for (int j = 0; j < 8; j += 2) {
            ulonglong2 u = w4[j];
            ulonglong2 v = w4[j + 1];
            A2[2 * j]     = ffma2(ns2, u.x, A2[2 * j]);
            A2[2 * j + 1] = ffma2(ns2, u.y, A2[2 * j + 1]);
            A2[2 * j + 2] = ffma2(ns2, v.x, A2[2 * j + 2]);
            A2[2 * j + 3] = ffma2(ns2, v.y, A2[2 * j + 3]);
        }

        cur ^= 1;
    }
}

// ---------------------------------------------------------------------------
// Parallel log-sum of picked probabilities (one warp, tree reduction).
// ---------------------------------------------------------------------------
__global__ void logsum_kernel(float* __restrict__ out_scalar)
{
    int lane = threadIdx.x;
    float s = 0.0f;
    for (int k = lane; k < NN; k += 32) s += logf(g_picked[k]);
#pragma unroll
    for (int o = 16; o; o >>= 1) s += __shfl_xor_sync(0xffffffffu, s, o);
    if (lane == 0) *out_scalar = s;
}

extern "C" void kernel_launch(void* const* d_in, const int* in_sizes, int n_in,
                              void* d_out, int out_size)
{
    const float* P = (const float*)d_in[0];    // [D, N] float32
    const int* pos = (const int*)d_in[1];      // [N] int32, sorted
    float* out = (float*)d_out;                // [N*D probs][1 logprob]

    sampler_kernel<<<NN, 512>>>(P, pos, out);
    logsum_kernel<<<1, 32>>>(out + (out_size - 1));
}

// round 6
// speedup vs baseline: 2.6165x; 1.0315x over previous
#include <cuda_runtime.h>
#include <math.h>

#define DD 512
#define NN 128
#define TB 8

typedef unsigned long long ull;

__device__ float g_picked[NN];

// ---- packed f32x2 helpers (Blackwell FFMA2 path, PTX-only) -----------------
static __device__ __forceinline__ ull ffma2(ull a, ull b, ull c)
{
    ull d;
    asm("fma.rn.f32x2 %0, %1, %2, %3;" : "=l"(d) : "l"(a), "l"(b), "l"(c));
    return d;
}
static __device__ __forceinline__ ull pack2(float x, float y)
{
    ull d;
    asm("mov.b64 %0, {%1, %2};" : "=l"(d) : "f"(x), "f"(y));
    return d;
}
static __device__ __forceinline__ void unpack2(ull v, float& x, float& y)
{
    asm("mov.b64 {%0, %1}, %2;" : "=f"(x), "=f"(y) : "l"(v));
}

// ---------------------------------------------------------------------------
// One CTA (512 threads) per output row k; register-resident Omega (128x128),
// blocked Sherman-Morrison elimination with T=8 sites per block:
//   W = Omega*Ptile  -> S = Ptile^T*W (8x8) -> tiny LU on S (warp0, emits
//   probs) -> forward-substitute Y -> rank-8 update of Omega.
// Thread (r,h) owns Omega[r][h*32 .. h*32+31] as 16 packed f32x2 registers.
// NOTE: rows of pv_s / wfin / Y_s are 128 floats = 32 ulonglong2 — row stride
// in ulonglong2 units is 32 (this was the R5 bug).
// ---------------------------------------------------------------------------
__global__ void __launch_bounds__(512, 1)
sampler_kernel(const float* __restrict__ P, const int* __restrict__ pos,
               float* __restrict__ out)
{
    __shared__ __align__(16) float pv_s[2][TB][NN];
    __shared__ __align__(16) float wpart[TB][512];
    __shared__ __align__(16) float wfin[TB][NN];
    __shared__ __align__(16) float Y_s[TB][NN];
    __shared__ float S_s[TB * TB];
    __shared__ float L_s[TB][TB];
    __shared__ float rd_s[TB];
    __shared__ unsigned char occ[DD];

    const int k    = blockIdx.x;
    const int tid  = threadIdx.x;
    const int r    = tid & 127;
    const int h    = tid >> 7;        // column quarter 0..3
    const int lane = tid & 31;
    const int wid  = tid >> 5;        // 0..15

    for (int i = tid; i < DD; i += 512) occ[i] = 0;
    __syncthreads();
    if (tid < NN) occ[pos[tid]] = 1;

    const int myPos = pos[k];
    const int xmin  = (k == 0) ? 0 : (pos[k - 1] + 1);
    const int xmax  = DD - NN + k + 1;

    for (int i = tid; i < DD; i += 512) out[k * DD + i] = 0.0f;

    // Omega = I
    ull A2[16];
#pragma unroll
    for (int j = 0; j < 16; j++) {
        int c0 = h * 32 + 2 * j;
        A2[j] = pack2((c0 == r) ? 1.0f : 0.0f, (c0 + 1 == r) ? 1.0f : 0.0f);
    }

    // stage first block's 8 P rows (1024 floats = 256 float4, threads 256..511)
    if (tid >= 256)
        ((float4*)&pv_s[0][0][0])[tid - 256] = __ldg((const float4*)P + (tid - 256));
    __syncthreads();

    float cprod = 1.0f;                 // meaningful in warp0 lane0 only
    int buf = 0;
    for (int i0 = 0; i0 < xmax; i0 += TB) {
        const bool last = (i0 + TB >= xmax);

        // prefetch next block's P rows
        float4 pf;
        if (tid >= 256 && !last)
            pf = __ldg((const float4*)(P + (i0 + TB) * NN) + (tid - 256));

        // ---- phase 1: W-partials. acc[b] = sum over owned 32 cols of
        //      Omega[r][c] * Ptile[b][c].  Row stride = 32 ulonglong2.
        ull acc2[TB];
#pragma unroll
        for (int b = 0; b < TB; b++) acc2[b] = 0ull;
        {
            const ulonglong2* base = (const ulonglong2*)&pv_s[buf][0][h * 32];
#pragma unroll
            for (int j = 0; j < 8; j++) {
#pragma unroll
                for (int b = 0; b < TB; b++) {
                    ulonglong2 u = base[b * 32 + j];
                    acc2[b] = ffma2(A2[2 * j],     u.x, acc2[b]);
                    acc2[b] = ffma2(A2[2 * j + 1], u.y, acc2[b]);
                }
            }
        }
#pragma unroll
        for (int b = 0; b < TB; b++) {
            float x, y;
            unpack2(acc2[b], x, y);
            wpart[b][tid] = x + y;
        }
        __syncthreads();                               // --- b1 ---

        // stage next block's P rows into the other buffer
        if (tid >= 256 && !last)
            ((float4*)&pv_s[buf ^ 1][0][0])[tid - 256] = pf;

        // ---- wfin[b][r] = full W[r][b] (reduce the 4 column quarters)
#pragma unroll
        for (int s = 0; s < 2; s++) {
            int b = h * 2 + s;
            wfin[b][r] = (wpart[b][r] + wpart[b][r + 128])
                       + (wpart[b][r + 256] + wpart[b][r + 384]);
        }
        __syncthreads();                               // --- b2 ---

        // ---- S[a][b] = sum_r Ptile[a][r] * wfin[b][r]; each warp: 4 entries
        {
            float t0, t1, t2, t3;
            const int e0 = wid * 4;
            {
                int a = (e0 + 0) >> 3, b = (e0 + 0) & 7;
                float4 pa = ((const float4*)&pv_s[buf][a][0])[lane];
                float4 wb = ((const float4*)&wfin[b][0])[lane];
                t0 = pa.x * wb.x + pa.y * wb.y + pa.z * wb.z + pa.w * wb.w;
            }
            {
                int a = (e0 + 1) >> 3, b = (e0 + 1) & 7;
                float4 pa = ((const float4*)&pv_s[buf][a][0])[lane];
                float4 wb = ((const float4*)&wfin[b][0])[lane];
                t1 = pa.x * wb.x + pa.y * wb.y + pa.z * wb.z + pa.w * wb.w;
            }
            {
                int a = (e0 + 2) >> 3, b = (e0 + 2) & 7;
                float4 pa = ((const float4*)&pv_s[buf][a][0])[lane];
                float4 wb = ((const float4*)&wfin[b][0])[lane];
                t2 = pa.x * wb.x + pa.y * wb.y + pa.z * wb.z + pa.w * wb.w;
            }
            {
                int a = (e0 + 3) >> 3, b = (e0 + 3) & 7;
                float4 pa = ((const float4*)&pv_s[buf][a][0])[lane];
                float4 wb = ((const float4*)&wfin[b][0])[lane];
                t3 = pa.x * wb.x + pa.y * wb.y + pa.z * wb.z + pa.w * wb.w;
            }
#pragma unroll
            for (int o = 16; o; o >>= 1) {
                t0 += __shfl_xor_sync(0xffffffffu, t0, o);
                t1 += __shfl_xor_sync(0xffffffffu, t1, o);
                t2 += __shfl_xor_sync(0xffffffffu, t2, o);
                t3 += __shfl_xor_sync(0xffffffffu, t3, o);
            }
            if (lane == 0) {
                S_s[e0 + 0] = t0; S_s[e0 + 1] = t1;
                S_s[e0 + 2] = t2; S_s[e0 + 3] = t3;
            }
        }
        __syncthreads();                               // --- b3 ---

        // ---- tiny LU on S (warp0): betas -> emissions, multipliers L, 1/d
        if (wid == 0) {
            const int Teff = last ? (xmax - i0) : TB;
            float S_row[TB];
#pragma unroll
            for (int b = 0; b < TB; b++) S_row[b] = 0.0f;
            if (lane < TB) {
#pragma unroll
                for (int b = 0; b < TB; b++) S_row[b] = S_s[lane * TB + b];
            }
            float cp = cprod;
            for (int j = 0; j < Teff; j++) {
                float rj[TB];
#pragma unroll
                for (int b = 0; b < TB; b++)
                    rj[b] = __shfl_sync(0xffffffffu, S_row[b], j);
                const float beta = rj[j];
                const int i = i0 + j;
                const bool inwin = (i >= xmin);
                if (lane == 0 && inwin) {
                    float prob = cp * beta;
                    float pcl = (fabsf(prob) > 1e-15f) ? prob : 0.0f;
                    out[k * DD + i] = pcl;
                    if (i == myPos) g_picked[k] = pcl;
                }
                if (inwin) cp *= (1.0f - beta);
                if (i == xmax - 1) break;   // forced site: stop, no elimination
                const float d  = (!inwin && occ[i]) ? beta : (beta - 1.0f);
                const float rd = 1.0f / d;
                if (lane < TB) L_s[lane][j] = rj[lane] * rd;
                if (lane == 0) rd_s[j] = rd;
                if (lane < TB) {
                    const float mult = rj[lane] * rd;
#pragma unroll
                    for (int b = 0; b < TB; b++)
                        S_row[b] = fmaf(-mult, rj[b], S_row[b]);
                }
            }
            cprod = cp;
        }
        __syncthreads();                               // --- b4 ---
        if (last) break;

        // ---- forward substitution: y_j = w_j - sum_{m<j} L[j][m] y_m
        if (tid < NN) {
            float y[TB];
#pragma unroll
            for (int j = 0; j < TB; j++) {
                float v = wfin[j][tid];
#pragma unroll
                for (int m = 0; m < TB; m++)
                    if (m < j) v = fmaf(-L_s[j][m], y[m], v);
                y[j] = v;
                Y_s[j][tid] = v;
            }
        }
        __syncthreads();                               // --- b5 ---

        // ---- rank-8 update: Omega -= sum_j y_j y_j^T / d_j
        //      (Y_s row stride = 32 ulonglong2)
        {
            float zr[TB];
#pragma unroll
            for (int j = 0; j < TB; j++) zr[j] = Y_s[j][r] * rd_s[j];
            const ulonglong2* ybase = (const ulonglong2*)&Y_s[0][h * 32];
#pragma unroll
            for (int j = 0; j < TB; j++) {
                ull nz = pack2(-zr[j], -zr[j]);
#pragma unroll
                for (int t = 0; t < 8; t++) {
                    ulonglong2 u = ybase[j * 32 + t];
                    A2[2 * t]     = ffma2(nz, u.x, A2[2 * t]);
                    A2[2 * t + 1] = ffma2(nz, u.y, A2[2 * t + 1]);
                }
            }
        }
        buf ^= 1;
    }
}

// ---------------------------------------------------------------------------
// Parallel log-sum of picked probabilities (one warp, tree reduction).
// ---------------------------------------------------------------------------
__global__ void logsum_kernel(float* __restrict__ out_scalar)
{
    int lane = threadIdx.x;
    float s = 0.0f;
    for (int k = lane; k < NN; k += 32) s += logf(g_picked[k]);
#pragma unroll
    for (int o = 16; o; o >>= 1) s += __shfl_xor_sync(0xffffffffu, s, o);
    if (lane == 0) *out_scalar = s;
}

extern "C" void kernel_launch(void* const* d_in, const int* in_sizes, int n_in,
                              void* d_out, int out_size)
{
    const float* P = (const float*)d_in[0];    // [D, N] float32
    const int* pos = (const int*)d_in[1];      // [N] int32, sorted
    float* out = (float*)d_out;                // [N*D probs][1 logprob]

    sampler_kernel<<<NN, 512>>>(P, pos, out);
    logsum_kernel<<<1, 32>>>(out + (out_size - 1));
}

// round 7
// speedup vs baseline: 2.6918x; 1.0288x over previous
#include <cuda_runtime.h>
#include <math.h>

#define DD 512
#define NN 128
#define TB 8

typedef unsigned long long ull;

__device__ float g_picked[NN];

// ---- packed f32x2 helpers (Blackwell FFMA2 path, PTX-only) -----------------
static __device__ __forceinline__ ull ffma2(ull a, ull b, ull c)
{
    ull d;
    asm("fma.rn.f32x2 %0, %1, %2, %3;" : "=l"(d) : "l"(a), "l"(b), "l"(c));
    return d;
}
static __device__ __forceinline__ ull pack2(float x, float y)
{
    ull d;
    asm("mov.b64 %0, {%1, %2};" : "=l"(d) : "f"(x), "f"(y));
    return d;
}
static __device__ __forceinline__ void unpack2(ull v, float& x, float& y)
{
    asm("mov.b64 {%0, %1}, %2;" : "=f"(x), "=f"(y) : "l"(v));
}

// ---------------------------------------------------------------------------
// One CTA (256 threads, 8 warps) per output row k.
// Omega (128x128, symmetric) register-resident as 2D tiles:
//   warp w owns rows [16w, 16w+16); lane: rh=lane&1 -> 8 rows r0=16w+8rh,
//   cg=lane>>1 -> 8 cols c0=8cg. Thread tile = 8x8 = A2[8][4] packed f32x2.
// Per TB=8-site block:
//   phase1: W = Omega*Ptile; row-sums via in-warp butterfly -> wreg2 (regs)
//           + wfin (smem, for Gram)
//   gram:   S[w][b] = p_w . w_b   (one S row per warp)
//   LU:     8x8 LU on S done warp-locally by EVERY warp (symmetry:
//           mult = S_row[j]*rd). Warp0 lane0 emits probs.
//   fwdsub: y_j = w_j - sum L[j][m] y_m computed IN REGISTERS on owned rows;
//           Y written to smem by 2 lanes/warp (cols side only).
//   update: Omega -= sum_j (y_j*rd_j) y_j^T  (rows from regs, cols from smem)
// ---------------------------------------------------------------------------
__global__ void __launch_bounds__(256, 1)
sampler_kernel(const float* __restrict__ P, const int* __restrict__ pos,
               float* __restrict__ out)
{
    __shared__ __align__(16) float pv_s[2][TB][NN];
    __shared__ __align__(16) float wfin[TB][NN];
    __shared__ __align__(16) float Y_s[TB][NN];
    __shared__ __align__(16) float S_s[TB * TB];
    __shared__ unsigned char occ[DD];

    const int k    = blockIdx.x;
    const int tid  = threadIdx.x;
    const int lane = tid & 31;
    const int wid  = tid >> 5;            // 0..7
    const int rh   = lane & 1;
    const int cg   = lane >> 1;           // 0..15
    const int r0   = wid * 16 + rh * 8;   // first owned row
    const int c0   = cg * 8;              // first owned col

    for (int i = tid; i < DD; i += 256) occ[i] = 0;
    __syncthreads();
    if (tid < NN) occ[pos[tid]] = 1;

    const int myPos = pos[k];
    const int xmin  = (k == 0) ? 0 : (pos[k - 1] + 1);
    const int xmax  = DD - NN + k + 1;

    for (int i = tid; i < DD; i += 256) out[k * DD + i] = 0.0f;

    // Omega = I : A2[r][q] covers (row r0+r, cols c0+2q, c0+2q+1)
    ull A2[8][4];
#pragma unroll
    for (int r = 0; r < 8; r++) {
        int rr = r0 + r;
#pragma unroll
        for (int q = 0; q < 4; q++)
            A2[r][q] = pack2((rr == c0 + 2 * q) ? 1.0f : 0.0f,
                             (rr == c0 + 2 * q + 1) ? 1.0f : 0.0f);
    }

    // stage first block's 8 P rows: 1024 floats = 256 float4, 1 per thread
    ((float4*)&pv_s[0][0][0])[tid] = __ldg((const float4*)P + tid);
    __syncthreads();

    float cprod = 1.0f;
    int buf = 0;
    for (int i0 = 0; i0 < xmax; i0 += TB) {
        const bool last = (i0 + TB >= xmax);

        float4 pf;
        if (!last) pf = __ldg((const float4*)(P + (i0 + TB) * NN) + tid);

        // ---- phase 1: per tile-row b, partial dot over 8 owned cols, then
        //      butterfly over the 16 col-groups -> full w_b for 8 owned rows.
        ull wreg2[TB][4];
#pragma unroll
        for (int b = 0; b < TB; b++) {
            ulonglong2 u = *(const ulonglong2*)&pv_s[buf][b][c0];
            ulonglong2 v = *(const ulonglong2*)&pv_s[buf][b][c0 + 4];
            float t[8];
#pragma unroll
            for (int r = 0; r < 8; r++) {
                ull acc = ffma2(A2[r][0], u.x, 0ull);
                acc = ffma2(A2[r][1], u.y, acc);
                acc = ffma2(A2[r][2], v.x, acc);
                acc = ffma2(A2[r][3], v.y, acc);
                float x, y;
                unpack2(acc, x, y);
                t[r] = x + y;
            }
#pragma unroll
            for (int off = 2; off <= 16; off <<= 1) {
#pragma unroll
                for (int r = 0; r < 8; r++)
                    t[r] += __shfl_xor_sync(0xffffffffu, t[r], off);
            }
#pragma unroll
            for (int q = 0; q < 4; q++)
                wreg2[b][q] = pack2(t[2 * q], t[2 * q + 1]);
            if (lane < 2) {
                *(float4*)&wfin[b][r0]     = make_float4(t[0], t[1], t[2], t[3]);
                *(float4*)&wfin[b][r0 + 4] = make_float4(t[4], t[5], t[6], t[7]);
            }
        }
        __syncthreads();                               // --- b1 ---

        if (!last) ((float4*)&pv_s[buf ^ 1][0][0])[tid] = pf;

        // ---- Gram: warp w computes S[w][b] = sum_r Ptile[w][r] * wfin[b][r]
        {
            float4 pa = ((const float4*)&pv_s[buf][wid][0])[lane];
            float sg[TB];
#pragma unroll
            for (int b = 0; b < TB; b++) {
                float4 wb = ((const float4*)&wfin[b][0])[lane];
                sg[b] = pa.x * wb.x + pa.y * wb.y + pa.z * wb.z + pa.w * wb.w;
            }
#pragma unroll
            for (int off = 1; off <= 16; off <<= 1) {
#pragma unroll
                for (int b = 0; b < TB; b++)
                    sg[b] += __shfl_xor_sync(0xffffffffu, sg[b], off);
            }
            if (lane == 0) {
                *(float4*)&S_s[wid * TB]     = make_float4(sg[0], sg[1], sg[2], sg[3]);
                *(float4*)&S_s[wid * TB + 4] = make_float4(sg[4], sg[5], sg[6], sg[7]);
            }
        }
        __syncthreads();                               // --- b2 ---

        // ---- warp-local 8x8 LU on S (every warp; deterministic & identical)
        //      lane a<8 holds S_row[b] = S[a][b]. Symmetry: mult_a = S_row[j]*rd.
        const int Teff = last ? (xmax - i0) : TB;
        float S_row[TB];
#pragma unroll
        for (int b = 0; b < TB; b++)
            S_row[b] = (lane < TB) ? S_s[lane * TB + b] : 0.0f;
        float Lcol[TB];           // Lcol[m] on lane a = L[a][m]
        float rdv[TB];
        float cp = cprod;
#pragma unroll
        for (int j = 0; j < TB; j++) {
            if (j >= Teff) break;
            float rj[TB];
#pragma unroll
            for (int b = 0; b < TB; b++)
                rj[b] = __shfl_sync(0xffffffffu, S_row[b], j);
            const float beta = rj[j];
            const int i = i0 + j;
            const bool inwin = (i >= xmin);
            if (wid == 0 && lane == 0 && inwin) {
                float prob = cp * beta;
                float pcl = (fabsf(prob) > 1e-15f) ? prob : 0.0f;
                out[k * DD + i] = pcl;
                if (i == myPos) g_picked[k] = pcl;
            }
            if (inwin) cp *= (1.0f - beta);
            if (i == xmax - 1) break;      // forced last site: no elimination
            const float d  = (!inwin && occ[i]) ? beta : (beta - 1.0f);
            const float rd = 1.0f / d;
            rdv[j] = rd;
            const float mult = S_row[j] * rd;   // = L[lane][j] by symmetry
            Lcol[j] = mult;
#pragma unroll
            for (int b = 0; b < TB; b++)
                S_row[b] = fmaf(-mult, rj[b], S_row[b]);
        }
        cprod = cp;
        if (last) break;

        // ---- forward substitution on owned rows (in registers):
        //      y_j = w_j - sum_{m<j} L[j][m] y_m ; L[j][m] via shfl from lane j
#pragma unroll
        for (int j = 1; j < TB; j++) {
#pragma unroll
            for (int m = 0; m < j; m++) {
                float ljm = __shfl_sync(0xffffffffu, Lcol[m], j);
                ull nl = pack2(-ljm, -ljm);
#pragma unroll
                for (int q = 0; q < 4; q++)
                    wreg2[j][q] = ffma2(nl, wreg2[m][q], wreg2[j][q]);
            }
        }
        // publish Y (cols side) — 2 lanes per warp cover the warp's 16 rows
        if (lane < 2) {
#pragma unroll
            for (int j = 0; j < TB; j++) {
                ulonglong2 w01; w01.x = wreg2[j][0]; w01.y = wreg2[j][1];
                ulonglong2 w23; w23.x = wreg2[j][2]; w23.y = wreg2[j][3];
                *(ulonglong2*)&Y_s[j][r0]     = w01;
                *(ulonglong2*)&Y_s[j][r0 + 4] = w23;
            }
        }
        __syncthreads();                               // --- b3 ---

        // ---- rank-8 update: Omega -= sum_j (y_j * rd_j) y_j^T
        //      rows (z) from registers, cols from Y_s (8 floats/j)
#pragma unroll
        for (int j = 0; j < TB; j++) {
            ulonglong2 yu = *(const ulonglong2*)&Y_s[j][c0];
            ulonglong2 yv = *(const ulonglong2*)&Y_s[j][c0 + 4];
            const float nrd = -rdv[j];
#pragma unroll
            for (int q = 0; q < 4; q++) {
                float zr0, zr1;
                unpack2(wreg2[j][q], zr0, zr1);
                float m0 = zr0 * nrd, m1 = zr1 * nrd;
                ull nz0 = pack2(m0, m0);
                ull nz1 = pack2(m1, m1);
                A2[2 * q][0]     = ffma2(nz0, yu.x, A2[2 * q][0]);
                A2[2 * q][1]     = ffma2(nz0, yu.y, A2[2 * q][1]);
                A2[2 * q][2]     = ffma2(nz0, yv.x, A2[2 * q][2]);
                A2[2 * q][3]     = ffma2(nz0, yv.y, A2[2 * q][3]);
                A2[2 * q + 1][0] = ffma2(nz1, yu.x, A2[2 * q + 1][0]);
                A2[2 * q + 1][1] = ffma2(nz1, yu.y, A2[2 * q + 1][1]);
                A2[2 * q + 1][2] = ffma2(nz1, yv.x, A2[2 * q + 1][2]);
                A2[2 * q + 1][3] = ffma2(nz1, yv.y, A2[2 * q + 1][3]);
            }
        }
        buf ^= 1;
    }
}

// ---------------------------------------------------------------------------
// Parallel log-sum of picked probabilities (one warp, tree reduction).
// ---------------------------------------------------------------------------
__global__ void logsum_kernel(float* __restrict__ out_scalar)
{
    int lane = threadIdx.x;
    float s = 0.0f;
    for (int k = lane; k < NN; k += 32) s += logf(g_picked[k]);
#pragma unroll
    for (int o = 16; o; o >>= 1) s += __shfl_xor_sync(0xffffffffu, s, o);
    if (lane == 0) *out_scalar = s;
}

extern "C" void kernel_launch(void* const* d_in, const int* in_sizes, int n_in,
                              void* d_out, int out_size)
{
    const float* P = (const float*)d_in[0];    // [D, N] float32
    const int* pos = (const int*)d_in[1];      // [N] int32, sorted
    float* out = (float*)d_out;                // [N*D probs][1 logprob]

    sampler_kernel<<<NN, 256>>>(P, pos, out);
    logsum_kernel<<<1, 32>>>(out + (out_size - 1));
}